// round 14
// baseline (speedup 1.0000x reference)
#include <cuda_runtime.h>
#include <cuda_bf16.h>
#include <stdint.h>
#include <math.h>

// ---------------- scratch ----------------
__device__ __align__(16) float         g_votes[(size_t)64 * 4096 * 256]; // [n][pix][cout]
__device__ __align__(16) __nv_bfloat16 g_xh[(size_t)64 * 4096 * 32];     // [n][h][w][cin] hi
__device__ __align__(16) __nv_bfloat16 g_xl[(size_t)64 * 4096 * 32];     // lo
__device__ __align__(16) __nv_bfloat16 g_wb[25 * 2 * 8192];              // [s][prec][swizzled 256x32]

// ---------------- helpers ----------------
__device__ __forceinline__ void cp16(uint32_t dst, const void* src, int sz) {
    asm volatile("cp.async.cg.shared.global [%0], [%1], 16, %2;"
                 :: "r"(dst), "l"(src), "r"(sz));
}
__device__ __forceinline__ void cp_commit() { asm volatile("cp.async.commit_group;" ::: "memory"); }
template <int N> __device__ __forceinline__ void cp_wait() {
    asm volatile("cp.async.wait_group %0;" :: "n"(N) : "memory");
}
__device__ __forceinline__ void ldsm4(uint32_t* r, uint32_t addr) {
    asm volatile("ldmatrix.sync.aligned.m8n8.x4.shared.b16 {%0,%1,%2,%3}, [%4];"
                 : "=r"(r[0]), "=r"(r[1]), "=r"(r[2]), "=r"(r[3]) : "r"(addr));
}
__device__ __forceinline__ void mma16816(float* c, const uint32_t* a, const uint32_t* b) {
    asm volatile("mma.sync.aligned.m16n8k16.row.col.f32.bf16.bf16.f32 "
                 "{%0,%1,%2,%3}, {%4,%5,%6,%7}, {%8,%9}, {%0,%1,%2,%3};"
                 : "+f"(c[0]), "+f"(c[1]), "+f"(c[2]), "+f"(c[3])
                 : "r"(a[0]), "r"(a[1]), "r"(a[2]), "r"(a[3]), "r"(b[0]), "r"(b[1]));
}
// XOR swizzle for B tiles: rows of 64B (4x16B chunks) paired into 128B lines.
__device__ __forceinline__ uint32_t swz(int row, int c) {
    return ((row >> 1) << 7) + (((((row & 1) << 2) | c) ^ ((row >> 1) & 7)) << 4);
}
__device__ __forceinline__ float wred(float x) {
#pragma unroll
    for (int o = 16; o; o >>= 1) x += __shfl_xor_sync(0xFFFFFFFFu, x, o);
    return x;
}

// ---------------- merged prep: x transpose/split + W swizzle/split ----------------
__global__ __launch_bounds__(256) void prep_kernel(const float* __restrict__ x,
                                                   const float* __restrict__ W) {
    __shared__ float sT[32 * 65];
    const int tid = threadIdx.x;
    if (blockIdx.x < 4096) {
        const int n = blockIdx.x >> 6, h = blockIdx.x & 63;
#pragma unroll
        for (int k = 0; k < 8; ++k) {
            int idx = tid + k * 256;              // 2048 = 32 cin x 64 w
            int cin = idx >> 6, w = idx & 63;
            sT[cin * 65 + w] = x[((size_t)(n * 32 + cin)) * 4096 + h * 64 + w];
        }
        __syncthreads();
#pragma unroll
        for (int k = 0; k < 8; ++k) {
            int idx = tid + k * 256;
            int w = idx >> 5, cin = idx & 31;
            float v = sT[cin * 65 + w];
            __nv_bfloat16 hi = __float2bfloat16(v);
            float lo = v - __bfloat162float(hi);
            size_t o = ((size_t)blockIdx.x * 64 + w) * 32 + cin;
            g_xh[o] = hi;
            g_xl[o] = __float2bfloat16(lo);
        }
    } else {
        const int s = blockIdx.x - 4096;          // shift 0..24
        for (int e = tid; e < 16384; e += 256) {
            int prec = e >> 13, rem = e & 8191;
            int q = rem >> 3, i = rem & 7;        // 16B chunk q, element i
            int line = q >> 3, cf = q & 7;
            int t = cf ^ (line & 7);
            int row = line * 2 + (t >> 2);        // cout 0..255
            int c = t & 3;                        // cin chunk
            int cin = c * 8 + i;
            float v = W[row * 800 + cin * 25 + s];
            __nv_bfloat16 hi = __float2bfloat16(v);
            __nv_bfloat16 o = prec ? __float2bfloat16(v - __bfloat162float(hi)) : hi;
            g_wb[(s * 2 + prec) * 8192 + rem] = o;
        }
    }
}

// ---------------- conv: mma.sync bf16 implicit GEMM, 3-product hi/lo --------------
// (R12 structure — measured best. A halo static, hoisted A-LDSM, 3-slot B ring.)
#define SA_BYTES 32640
#define SB_OFF   65280
#define SB_SLOT  16384
__global__ __launch_bounds__(256, 2) void conv_mma_kernel() {
    extern __shared__ char smem[];
    const uint32_t sb  = (uint32_t)__cvta_generic_to_shared(smem);
    const uint32_t sAh = sb, sAl = sb + SA_BYTES, sB = sb + SB_OFF;
    const int tid = threadIdx.x, wid = tid >> 5, lane = tid & 31;
    const int bx = blockIdx.x;
    const int nh = bx & 1;
    const int strip = bx >> 1;
    const int n = strip >> 5, h0 = (strip & 31) * 2;

    const __nv_bfloat16* xh = g_xh + (size_t)n * 4096 * 32;
    const __nv_bfloat16* xl = g_xl + (size_t)n * 4096 * 32;

    for (int i = tid; i < 1632; i += 256) {
        int cell = i >> 2, ch = i & 3;
        int r = cell / 68, c = cell - r * 68;
        int gh = h0 + r - 2, gw = c - 2;
        bool ok = ((unsigned)gh < 64u) && ((unsigned)gw < 64u);
        long eo = ok ? ((long)(gh * 64 + gw) * 32 + ch * 8) : 0;
        int sz = ok ? 16 : 0;
        uint32_t off = (uint32_t)(r * 68 + c) * 80 + ch * 16;
        cp16(sAh + off, xh + eo, sz);
        cp16(sAl + off, xl + eo, sz);
    }
    cp_commit();

    const char* wbase = (const char*)g_wb + nh * 8192;
    auto loadB = [&](int s, int slot) {
        const char* ws = wbase + (size_t)s * 32768;
        uint32_t d = sB + slot * SB_SLOT;
#pragma unroll
        for (int j = 0; j < 2; ++j) {
            uint32_t off = (uint32_t)(tid + j * 256) * 16;
            cp16(d + off,        ws + off,         16);
            cp16(d + 8192 + off, ws + 16384 + off, 16);
        }
    };
    loadB(0, 0); cp_commit();
    loadB(1, 1); cp_commit();

    const int mrow0 = (wid >> 1) * 32;
    const int ncol0 = (wid & 1) * 64;
    const int arow_off = (lane & 7) + ((lane >> 3) & 1) * 8;
    const int ac_off   = lane >> 4;
    const int brow_off = (lane & 7) + ((lane >> 4) << 3);
    const int bc_off   = (lane >> 3) & 1;

    int LA[2];
#pragma unroll
    for (int mt = 0; mt < 2; ++mt) {
        int m = mrow0 + mt * 16 + arow_off;
        LA[mt] = (m >> 6) * 68 + (m & 63);
    }

    float cacc[2][8][4];
#pragma unroll
    for (int a = 0; a < 2; ++a)
#pragma unroll
        for (int b = 0; b < 8; ++b)
#pragma unroll
            for (int d = 0; d < 4; ++d) cacc[a][b][d] = 0.0f;

#pragma unroll 1
    for (int s = 0; s < 25; ++s) {
        const int slot = s % 3;
        if (s < 24) cp_wait<1>(); else cp_wait<0>();
        __syncthreads();
        if (s + 2 < 25) { loadB(s + 2, (s + 2) % 3); cp_commit(); }

        const int ky = s / 5, kx = s - 5 * ky;
        const int soff = ky * 68 + kx;
        uint32_t arow[2];
#pragma unroll
        for (int mt = 0; mt < 2; ++mt) arow[mt] = (uint32_t)(LA[mt] + soff) * 80;

        uint32_t ah[2][2][4], al[2][2][4];
#pragma unroll
        for (int ks = 0; ks < 2; ++ks) {
            const uint32_t achunk = (uint32_t)(ks * 2 + ac_off) * 16;
#pragma unroll
            for (int mt = 0; mt < 2; ++mt) {
                ldsm4(ah[ks][mt], sAh + arow[mt] + achunk);
                ldsm4(al[ks][mt], sAl + arow[mt] + achunk);
            }
        }

        const uint32_t bbase = sB + slot * SB_SLOT;
#pragma unroll
        for (int ks = 0; ks < 2; ++ks) {
            const int cB = ks * 2 + bc_off;
#pragma unroll
            for (int nt = 0; nt < 4; ++nt) {
                uint32_t o = swz(ncol0 + nt * 16 + brow_off, cB);
                uint32_t bh[4], bl[4];
                ldsm4(bh, bbase + o);
                ldsm4(bl, bbase + 8192 + o);
#pragma unroll
                for (int mt = 0; mt < 2; ++mt) {
                    mma16816(cacc[mt][2 * nt],     ah[ks][mt], bh);
                    mma16816(cacc[mt][2 * nt + 1], ah[ks][mt], bh + 2);
                    mma16816(cacc[mt][2 * nt],     al[ks][mt], bh);
                    mma16816(cacc[mt][2 * nt + 1], al[ks][mt], bh + 2);
                    mma16816(cacc[mt][2 * nt],     ah[ks][mt], bl);
                    mma16816(cacc[mt][2 * nt + 1], ah[ks][mt], bl + 2);
                }
            }
        }
    }

    const int g = lane >> 2, cc = (lane & 3) * 2;
#pragma unroll
    for (int mt = 0; mt < 2; ++mt) {
#pragma unroll
        for (int half = 0; half < 2; ++half) {
            int m = mrow0 + mt * 16 + g + half * 8;
            int pix = (h0 + (m >> 6)) * 64 + (m & 63);
            float* vp = g_votes + ((size_t)n * 4096 + pix) * 256 + nh * 128 + ncol0 + cc;
#pragma unroll
            for (int n8 = 0; n8 < 8; ++n8) {
                float2 v = make_float2(cacc[mt][n8][half * 2], cacc[mt][n8][half * 2 + 1]);
                *(float2*)(vp + n8 * 8) = v;
            }
        }
    }
}

// ---------------- routing v4: 4 warps per pixel (2 nc per warp) ----------------
// Warp quarter q owns out-caps {2q, 2q+1}: v[8][2]=16 regs -> ~58 regs ->
// launch_bounds(256,4) -> 32 warps/SM. Logits exchanged via smem per pixel
// (128-thread named barrier). Reduction trees identical to R13 (bit-exact).
// CTA = 2 pixels, 8 warps.
__global__ __launch_bounds__(256, 4) void routing_kernel(const float* __restrict__ bias,
                                                         float* __restrict__ out) {
    extern __shared__ float rsm[];          // sv 4096 | ex 128 | sact 512 floats
    float* sv   = rsm;
    float* ex   = rsm + 4096;
    float* sact = rsm + 4224;
    const uint32_t svb = (uint32_t)__cvta_generic_to_shared(rsm);

    const int tid = threadIdx.x, warp = tid >> 5, lane = tid & 31;
    const int q = warp & 3, pixloc = warp >> 2;        // nc-quarter, pixel 0/1
    const int b = blockIdx.x >> 11, h = (blockIdx.x >> 5) & 63, wp = blockIdx.x & 31;
    const int pixbase = h * 64 + wp * 2;
    const int pix = pixbase + pixloc;

    // warp slice: 8 ic x 64 couts (quarter q) = 2KB; lanes 0..15 cp16
    if (lane < 16) {
#pragma unroll
        for (int ic = 0; ic < 8; ++ic) {
            const float* src = g_votes + ((size_t)(b * 8 + ic) * 4096 + pix) * 256
                             + q * 64 + lane * 4;
            cp16(svb + (uint32_t)(pixloc * 8192 + ic * 1024 + q * 256 + lane * 16), src, 16);
        }
    }
    cp_commit();

    float bv[2];
#pragma unroll
    for (int ncl = 0; ncl < 2; ++ncl) bv[ncl] = bias[(q * 2 + ncl) * 32 + lane];

    cp_wait<0>();
    __syncwarp();

    float v[8][2];
    const float* svp = sv + pixloc * 2048 + q * 64;
#pragma unroll
    for (int ic = 0; ic < 8; ++ic)
#pragma unroll
        for (int ncl = 0; ncl < 2; ++ncl)
            v[ic][ncl] = svp[ic * 256 + ncl * 32 + lane];

    const int my_ic = lane & 7;
    float lg[2] = {0.0f, 0.0f};      // own logits (my_ic, our 2 ncs)
    float lgall[8];                  // all 8 nc logits of my_ic (from exchange)

    float a[2];
#pragma unroll 1
    for (int it = 0; it < 3; ++it) {
        float p[2];
#pragma unroll
        for (int ncl = 0; ncl < 2; ++ncl) p[ncl] = bv[ncl];

        if (it == 0) {               // softmax of zeros = 0.125 exactly
#pragma unroll
            for (int ic = 0; ic < 8; ++ic)
#pragma unroll
                for (int ncl = 0; ncl < 2; ++ncl)
                    p[ncl] += 0.125f * v[ic][ncl];
        } else {
            float mx = lgall[0];
#pragma unroll
            for (int k = 1; k < 8; ++k) mx = fmaxf(mx, lgall[k]);
            float ssum = 0.0f;
#pragma unroll
            for (int k = 0; k < 8; ++k) ssum += __expf(lgall[k] - mx);
            float inv = 1.0f / ssum;
            float r[2];
#pragma unroll
            for (int ncl = 0; ncl < 2; ++ncl)
                r[ncl] = __expf(lgall[q * 2 + ncl] - mx) * inv;
#pragma unroll
            for (int ic = 0; ic < 8; ++ic)
#pragma unroll
                for (int ncl = 0; ncl < 2; ++ncl)
                    p[ncl] += __shfl_sync(0xFFFFFFFFu, r[ncl], ic) * v[ic][ncl];
        }
#pragma unroll
        for (int ncl = 0; ncl < 2; ++ncl) {
            float s2 = wred(p[ncl] * p[ncl]);
            a[ncl] = p[ncl] * (sqrtf(s2) / (1.0f + s2));
        }

        if (it < 2) {
            // distances: 16 vars (ic*2+ncl), duplicated across the two lane
            // halves -> same xor16,8,4,2,1 tree per var as R13 (bit-exact).
            float z[16];
#pragma unroll
            for (int j = 0; j < 16; ++j) {
                int ic = j >> 1, ncl = j & 1;
                float pr = v[ic][ncl] * a[ncl];
                z[j] = pr + __shfl_xor_sync(0xFFFFFFFFu, pr, 16);
            }
#pragma unroll
            for (int o = 8; o; o >>= 1) {
#pragma unroll
                for (int j = 0; j < o; ++j) {
                    float send = (lane & o) ? z[j] : z[j + o];
                    float recv = __shfl_xor_sync(0xFFFFFFFFu, send, o);
                    z[j] = ((lane & o) ? z[j + o] : z[j]) + recv;
                }
            }
            // lane l holds var (l & 15); redistribute to (my_ic, ncl)
#pragma unroll
            for (int ncl = 0; ncl < 2; ++ncl)
                lg[ncl] += __shfl_sync(0xFFFFFFFFu, z[0], my_ic * 2 + ncl);

            // exchange logits across the 4 warps of this pixel
            if (lane < 8) {
                ex[pixloc * 64 + lane * 8 + q * 2]     = lg[0];
                ex[pixloc * 64 + lane * 8 + q * 2 + 1] = lg[1];
            }
            asm volatile("bar.sync %0, 128;" :: "r"(pixloc + 1) : "memory");
#pragma unroll
            for (int k = 0; k < 8; ++k)
                lgall[k] = ex[pixloc * 64 + my_ic * 8 + k];
        }
    }
#pragma unroll
    for (int ncl = 0; ncl < 2; ++ncl)
        sact[pixloc * 256 + (q * 2 + ncl) * 32 + lane] = a[ncl];
    __syncthreads();

    // out[b][cout][pixbase..+2): float2 per thread (tid = cout)
    float2 o2 = make_float2(sact[tid], sact[256 + tid]);
    *(float2*)(out + ((size_t)b * 256 + tid) * 4096 + pixbase) = o2;
}

// ---------------------------------------------------------------------------
extern "C" void kernel_launch(void* const* d_in, const int* in_sizes, int n_in,
                              void* d_out, int out_size)
{
    const float* x    = (const float*)d_in[0];  // [8,8,32,64,64]
    const float* Wt   = (const float*)d_in[1];  // [256,32,5,5]
    const float* bias = (const float*)d_in[2];  // [1,1,8,32]
    float* out = (float*)d_out;                 // [8,8,32,64,64]

    const int conv_smem = 2 * SA_BYTES + 3 * SB_SLOT;        // 114432
    const int rout_smem = (4096 + 128 + 512) * (int)sizeof(float);  // 18944
    cudaFuncSetAttribute(conv_mma_kernel,
                         cudaFuncAttributeMaxDynamicSharedMemorySize, conv_smem);
    cudaFuncSetAttribute(routing_kernel,
                         cudaFuncAttributeMaxDynamicSharedMemorySize, rout_smem);

    prep_kernel<<<4096 + 25, 256>>>(x, Wt);
    conv_mma_kernel<<<4096, 256, conv_smem>>>();
    routing_kernel<<<8 * 64 * 32, 256, rout_smem>>>(bias, out);
}

// round 15
// speedup vs baseline: 1.0493x; 1.0493x over previous
#include <cuda_runtime.h>
#include <cuda_bf16.h>
#include <stdint.h>
#include <math.h>

// ---------------- scratch ----------------
__device__ __align__(16) float         g_votes[(size_t)64 * 4096 * 256]; // [n][pix][cout]
__device__ __align__(16) __nv_bfloat16 g_xh[(size_t)64 * 4096 * 32];     // [n][h][w][cin] hi
__device__ __align__(16) __nv_bfloat16 g_xl[(size_t)64 * 4096 * 32];     // lo
__device__ __align__(16) __nv_bfloat16 g_wb[25 * 2 * 8192];              // [s][prec][swizzled 256x32]

// ---------------- helpers ----------------
__device__ __forceinline__ void cp16(uint32_t dst, const void* src, int sz) {
    asm volatile("cp.async.cg.shared.global [%0], [%1], 16, %2;"
                 :: "r"(dst), "l"(src), "r"(sz));
}
__device__ __forceinline__ void cp_commit() { asm volatile("cp.async.commit_group;" ::: "memory"); }
template <int N> __device__ __forceinline__ void cp_wait() {
    asm volatile("cp.async.wait_group %0;" :: "n"(N) : "memory");
}
__device__ __forceinline__ void ldsm4(uint32_t* r, uint32_t addr) {
    asm volatile("ldmatrix.sync.aligned.m8n8.x4.shared.b16 {%0,%1,%2,%3}, [%4];"
                 : "=r"(r[0]), "=r"(r[1]), "=r"(r[2]), "=r"(r[3]) : "r"(addr));
}
__device__ __forceinline__ void mma16816(float* c, const uint32_t* a, const uint32_t* b) {
    asm volatile("mma.sync.aligned.m16n8k16.row.col.f32.bf16.bf16.f32 "
                 "{%0,%1,%2,%3}, {%4,%5,%6,%7}, {%8,%9}, {%0,%1,%2,%3};"
                 : "+f"(c[0]), "+f"(c[1]), "+f"(c[2]), "+f"(c[3])
                 : "r"(a[0]), "r"(a[1]), "r"(a[2]), "r"(a[3]), "r"(b[0]), "r"(b[1]));
}
// XOR swizzle for B tiles: rows of 64B (4x16B chunks) paired into 128B lines.
__device__ __forceinline__ uint32_t swz(int row, int c) {
    return ((row >> 1) << 7) + (((((row & 1) << 2) | c) ^ ((row >> 1) & 7)) << 4);
}
__device__ __forceinline__ float wred(float x) {
#pragma unroll
    for (int o = 16; o; o >>= 1) x += __shfl_xor_sync(0xFFFFFFFFu, x, o);
    return x;
}

// ---------------- merged prep: x transpose/split + W swizzle/split ----------------
__global__ __launch_bounds__(256) void prep_kernel(const float* __restrict__ x,
                                                   const float* __restrict__ W) {
    __shared__ float sT[32 * 65];
    const int tid = threadIdx.x;
    if (blockIdx.x < 4096) {
        const int n = blockIdx.x >> 6, h = blockIdx.x & 63;
#pragma unroll
        for (int k = 0; k < 8; ++k) {
            int idx = tid + k * 256;              // 2048 = 32 cin x 64 w
            int cin = idx >> 6, w = idx & 63;
            sT[cin * 65 + w] = x[((size_t)(n * 32 + cin)) * 4096 + h * 64 + w];
        }
        __syncthreads();
#pragma unroll
        for (int k = 0; k < 8; ++k) {
            int idx = tid + k * 256;
            int w = idx >> 5, cin = idx & 31;
            float v = sT[cin * 65 + w];
            __nv_bfloat16 hi = __float2bfloat16(v);
            float lo = v - __bfloat162float(hi);
            size_t o = ((size_t)blockIdx.x * 64 + w) * 32 + cin;
            g_xh[o] = hi;
            g_xl[o] = __float2bfloat16(lo);
        }
    } else {
        const int s = blockIdx.x - 4096;          // shift 0..24
        for (int e = tid; e < 16384; e += 256) {
            int prec = e >> 13, rem = e & 8191;
            int q = rem >> 3, i = rem & 7;        // 16B chunk q, element i
            int line = q >> 3, cf = q & 7;
            int t = cf ^ (line & 7);
            int row = line * 2 + (t >> 2);        // cout 0..255
            int c = t & 3;                        // cin chunk
            int cin = c * 8 + i;
            float v = W[row * 800 + cin * 25 + s];
            __nv_bfloat16 hi = __float2bfloat16(v);
            __nv_bfloat16 o = prec ? __float2bfloat16(v - __bfloat162float(hi)) : hi;
            g_wb[(s * 2 + prec) * 8192 + rem] = o;
        }
    }
}

// ---------------- conv: mma.sync bf16 implicit GEMM, 3-product hi/lo --------------
// (R12 structure — measured best. A halo static, hoisted A-LDSM, 3-slot B ring.)
#define SA_BYTES 32640
#define SB_OFF   65280
#define SB_SLOT  16384
__global__ __launch_bounds__(256, 2) void conv_mma_kernel() {
    extern __shared__ char smem[];
    const uint32_t sb  = (uint32_t)__cvta_generic_to_shared(smem);
    const uint32_t sAh = sb, sAl = sb + SA_BYTES, sB = sb + SB_OFF;
    const int tid = threadIdx.x, wid = tid >> 5, lane = tid & 31;
    const int bx = blockIdx.x;
    const int nh = bx & 1;
    const int strip = bx >> 1;
    const int n = strip >> 5, h0 = (strip & 31) * 2;

    const __nv_bfloat16* xh = g_xh + (size_t)n * 4096 * 32;
    const __nv_bfloat16* xl = g_xl + (size_t)n * 4096 * 32;

    for (int i = tid; i < 1632; i += 256) {
        int cell = i >> 2, ch = i & 3;
        int r = cell / 68, c = cell - r * 68;
        int gh = h0 + r - 2, gw = c - 2;
        bool ok = ((unsigned)gh < 64u) && ((unsigned)gw < 64u);
        long eo = ok ? ((long)(gh * 64 + gw) * 32 + ch * 8) : 0;
        int sz = ok ? 16 : 0;
        uint32_t off = (uint32_t)(r * 68 + c) * 80 + ch * 16;
        cp16(sAh + off, xh + eo, sz);
        cp16(sAl + off, xl + eo, sz);
    }
    cp_commit();

    const char* wbase = (const char*)g_wb + nh * 8192;
    auto loadB = [&](int s, int slot) {
        const char* ws = wbase + (size_t)s * 32768;
        uint32_t d = sB + slot * SB_SLOT;
#pragma unroll
        for (int j = 0; j < 2; ++j) {
            uint32_t off = (uint32_t)(tid + j * 256) * 16;
            cp16(d + off,        ws + off,         16);
            cp16(d + 8192 + off, ws + 16384 + off, 16);
        }
    };
    loadB(0, 0); cp_commit();
    loadB(1, 1); cp_commit();

    const int mrow0 = (wid >> 1) * 32;
    const int ncol0 = (wid & 1) * 64;
    const int arow_off = (lane & 7) + ((lane >> 3) & 1) * 8;
    const int ac_off   = lane >> 4;
    const int brow_off = (lane & 7) + ((lane >> 4) << 3);
    const int bc_off   = (lane >> 3) & 1;

    int LA[2];
#pragma unroll
    for (int mt = 0; mt < 2; ++mt) {
        int m = mrow0 + mt * 16 + arow_off;
        LA[mt] = (m >> 6) * 68 + (m & 63);
    }

    float cacc[2][8][4];
#pragma unroll
    for (int a = 0; a < 2; ++a)
#pragma unroll
        for (int b = 0; b < 8; ++b)
#pragma unroll
            for (int d = 0; d < 4; ++d) cacc[a][b][d] = 0.0f;

#pragma unroll 1
    for (int s = 0; s < 25; ++s) {
        const int slot = s % 3;
        if (s < 24) cp_wait<1>(); else cp_wait<0>();
        __syncthreads();
        if (s + 2 < 25) { loadB(s + 2, (s + 2) % 3); cp_commit(); }

        const int ky = s / 5, kx = s - 5 * ky;
        const int soff = ky * 68 + kx;
        uint32_t arow[2];
#pragma unroll
        for (int mt = 0; mt < 2; ++mt) arow[mt] = (uint32_t)(LA[mt] + soff) * 80;

        uint32_t ah[2][2][4], al[2][2][4];
#pragma unroll
        for (int ks = 0; ks < 2; ++ks) {
            const uint32_t achunk = (uint32_t)(ks * 2 + ac_off) * 16;
#pragma unroll
            for (int mt = 0; mt < 2; ++mt) {
                ldsm4(ah[ks][mt], sAh + arow[mt] + achunk);
                ldsm4(al[ks][mt], sAl + arow[mt] + achunk);
            }
        }

        const uint32_t bbase = sB + slot * SB_SLOT;
#pragma unroll
        for (int ks = 0; ks < 2; ++ks) {
            const int cB = ks * 2 + bc_off;
#pragma unroll
            for (int nt = 0; nt < 4; ++nt) {
                uint32_t o = swz(ncol0 + nt * 16 + brow_off, cB);
                uint32_t bh[4], bl[4];
                ldsm4(bh, bbase + o);
                ldsm4(bl, bbase + 8192 + o);
#pragma unroll
                for (int mt = 0; mt < 2; ++mt) {
                    mma16816(cacc[mt][2 * nt],     ah[ks][mt], bh);
                    mma16816(cacc[mt][2 * nt + 1], ah[ks][mt], bh + 2);
                    mma16816(cacc[mt][2 * nt],     al[ks][mt], bh);
                    mma16816(cacc[mt][2 * nt + 1], al[ks][mt], bh + 2);
                    mma16816(cacc[mt][2 * nt],     ah[ks][mt], bl);
                    mma16816(cacc[mt][2 * nt + 1], ah[ks][mt], bl + 2);
                }
            }
        }
    }

    const int g = lane >> 2, cc = (lane & 3) * 2;
#pragma unroll
    for (int mt = 0; mt < 2; ++mt) {
#pragma unroll
        for (int half = 0; half < 2; ++half) {
            int m = mrow0 + mt * 16 + g + half * 8;
            int pix = (h0 + (m >> 6)) * 64 + (m & 63);
            float* vp = g_votes + ((size_t)n * 4096 + pix) * 256 + nh * 128 + ncol0 + cc;
#pragma unroll
            for (int n8 = 0; n8 < 8; ++n8) {
                float2 v = make_float2(cacc[mt][n8][half * 2], cacc[mt][n8][half * 2 + 1]);
                *(float2*)(vp + n8 * 8) = v;
            }
        }
    }
}

// ---------------- routing v3 (R13, measured best): warp-pair per pixel ----------
__global__ __launch_bounds__(256, 3) void routing_kernel(const float* __restrict__ bias,
                                                         float* __restrict__ out) {
    extern __shared__ float rsm[];          // sv 8192 | ex 256 | sact 1024 floats
    float* sv   = rsm;
    float* ex   = rsm + 8192;
    float* sact = rsm + 8448;
    const uint32_t svb = (uint32_t)__cvta_generic_to_shared(rsm);

    const int tid = threadIdx.x, warp = tid >> 5, lane = tid & 31;
    const int pairid = warp >> 1, nh = warp & 1;       // nh: which nc-half
    const int b = blockIdx.x >> 10, h = (blockIdx.x >> 4) & 63, wq = blockIdx.x & 15;
    const int pixbase = h * 64 + wq * 4;
    const int pix = pixbase + pairid;

    // warp-local cp.async: 8 ic x 128 couts (this warp's nc-half) = 4KB/warp
#pragma unroll
    for (int ic = 0; ic < 8; ++ic) {
        const float* src = g_votes + ((size_t)(b * 8 + ic) * 4096 + pix) * 256
                         + nh * 128 + lane * 4;
        cp16(svb + (uint32_t)(warp * 4096 + ic * 512 + lane * 16), src, 16);
    }
    cp_commit();

    float bv[4];
#pragma unroll
    for (int ncl = 0; ncl < 4; ++ncl) bv[ncl] = bias[(nh * 4 + ncl) * 32 + lane];

    cp_wait<0>();
    __syncwarp();

    float v[8][4];
    const float* svp = sv + warp * 1024;
#pragma unroll
    for (int ic = 0; ic < 8; ++ic)
#pragma unroll
        for (int ncl = 0; ncl < 4; ++ncl)
            v[ic][ncl] = svp[ic * 128 + ncl * 32 + lane];

    const int my_ic = lane & 7;
    float lg[4];
#pragma unroll
    for (int ncl = 0; ncl < 4; ++ncl) lg[ncl] = 0.0f;
    float lgo[4];
#pragma unroll
    for (int ncl = 0; ncl < 4; ++ncl) lgo[ncl] = 0.0f;

    float a[4];
#pragma unroll 1
    for (int it = 0; it < 3; ++it) {
        float p[4];
#pragma unroll
        for (int ncl = 0; ncl < 4; ++ncl) p[ncl] = bv[ncl];

        if (it == 0) {                       // softmax of zeros = 0.125 exactly
#pragma unroll
            for (int ic = 0; ic < 8; ++ic)
#pragma unroll
                for (int ncl = 0; ncl < 4; ++ncl)
                    p[ncl] += 0.125f * v[ic][ncl];
        } else {
            float mx = lg[0];
#pragma unroll
            for (int ncl = 1; ncl < 4; ++ncl) mx = fmaxf(mx, lg[ncl]);
#pragma unroll
            for (int ncl = 0; ncl < 4; ++ncl) mx = fmaxf(mx, lgo[ncl]);
            float ssum = 0.0f;
            float r[4];
#pragma unroll
            for (int ncl = 0; ncl < 4; ++ncl) { r[ncl] = __expf(lg[ncl] - mx); ssum += r[ncl]; }
#pragma unroll
            for (int ncl = 0; ncl < 4; ++ncl) ssum += __expf(lgo[ncl] - mx);
            float inv = 1.0f / ssum;
#pragma unroll
            for (int ncl = 0; ncl < 4; ++ncl) r[ncl] *= inv;
#pragma unroll
            for (int ic = 0; ic < 8; ++ic)
#pragma unroll
                for (int ncl = 0; ncl < 4; ++ncl)
                    p[ncl] += __shfl_sync(0xFFFFFFFFu, r[ncl], ic) * v[ic][ncl];
        }
#pragma unroll
        for (int ncl = 0; ncl < 4; ++ncl) {
            float s2 = wred(p[ncl] * p[ncl]);
            a[ncl] = p[ncl] * (sqrtf(s2) / (1.0f + s2));
        }

        if (it < 2) {
            float z[16];
#pragma unroll
            for (int j = 0; j < 16; ++j) {
                int ncl = j & 3, icl = j >> 2;
                float pA = v[icl][ncl]     * a[ncl];
                float pB = v[icl + 4][ncl] * a[ncl];
                float send = (lane & 16) ? pA : pB;
                float recv = __shfl_xor_sync(0xFFFFFFFFu, send, 16);
                z[j] = ((lane & 16) ? pB : pA) + recv;
            }
#pragma unroll
            for (int o = 8; o; o >>= 1) {
#pragma unroll
                for (int j = 0; j < o; ++j) {
                    float send = (lane & o) ? z[j] : z[j + o];
                    float recv = __shfl_xor_sync(0xFFFFFFFFu, send, o);
                    z[j] = ((lane & o) ? z[j + o] : z[j]) + recv;
                }
            }
#pragma unroll
            for (int ncl = 0; ncl < 4; ++ncl)
                lg[ncl] += __shfl_sync(0xFFFFFFFFu, z[0], my_ic * 4 + ncl);

            if (lane < 8) {
#pragma unroll
                for (int ncl = 0; ncl < 4; ++ncl)
                    ex[pairid * 64 + lane * 8 + nh * 4 + ncl] = lg[ncl];
            }
            asm volatile("bar.sync %0, 64;" :: "r"(pairid + 1) : "memory");
#pragma unroll
            for (int ncl = 0; ncl < 4; ++ncl)
                lgo[ncl] = ex[pairid * 64 + my_ic * 8 + (1 - nh) * 4 + ncl];
        }
    }
#pragma unroll
    for (int ncl = 0; ncl < 4; ++ncl)
        sact[pairid * 256 + (nh * 4 + ncl) * 32 + lane] = a[ncl];
    __syncthreads();

    float4 o4 = make_float4(sact[0 * 256 + tid], sact[1 * 256 + tid],
                            sact[2 * 256 + tid], sact[3 * 256 + tid]);
    *(float4*)(out + ((size_t)b * 256 + tid) * 4096 + pixbase) = o4;
}

// ---------------------------------------------------------------------------
extern "C" void kernel_launch(void* const* d_in, const int* in_sizes, int n_in,
                              void* d_out, int out_size)
{
    const float* x    = (const float*)d_in[0];  // [8,8,32,64,64]
    const float* Wt   = (const float*)d_in[1];  // [256,32,5,5]
    const float* bias = (const float*)d_in[2];  // [1,1,8,32]
    float* out = (float*)d_out;                 // [8,8,32,64,64]

    const int conv_smem = 2 * SA_BYTES + 3 * SB_SLOT;        // 114432
    const int rout_smem = (8192 + 256 + 1024) * (int)sizeof(float);  // 37888
    cudaFuncSetAttribute(conv_mma_kernel,
                         cudaFuncAttributeMaxDynamicSharedMemorySize, conv_smem);
    cudaFuncSetAttribute(routing_kernel,
                         cudaFuncAttributeMaxDynamicSharedMemorySize, rout_smem);

    prep_kernel<<<4096 + 25, 256>>>(x, Wt);
    conv_mma_kernel<<<4096, 256, conv_smem>>>();
    routing_kernel<<<8 * 64 * 16, 256, rout_smem>>>(bias, out);
}

// round 16
// speedup vs baseline: 1.0502x; 1.0009x over previous
#include <cuda_runtime.h>
#include <cuda_bf16.h>
#include <stdint.h>
#include <math.h>

// ---------------- scratch ----------------
__device__ __align__(16) float         g_votes[(size_t)64 * 4096 * 256]; // [n][pix][cout]
__device__ __align__(16) __nv_bfloat16 g_xh[(size_t)64 * 4096 * 32];     // [n][h][w][cin] hi
__device__ __align__(16) __nv_bfloat16 g_xl[(size_t)64 * 4096 * 32];     // lo
__device__ __align__(16) __nv_bfloat16 g_wb[25 * 2 * 8192];              // [s][prec][swizzled 256x32]

// ---------------- helpers ----------------
__device__ __forceinline__ void cp16(uint32_t dst, const void* src, int sz) {
    asm volatile("cp.async.cg.shared.global [%0], [%1], 16, %2;"
                 :: "r"(dst), "l"(src), "r"(sz));
}
__device__ __forceinline__ void cp_commit() { asm volatile("cp.async.commit_group;" ::: "memory"); }
template <int N> __device__ __forceinline__ void cp_wait() {
    asm volatile("cp.async.wait_group %0;" :: "n"(N) : "memory");
}
__device__ __forceinline__ void ldsm4(uint32_t* r, uint32_t addr) {
    asm volatile("ldmatrix.sync.aligned.m8n8.x4.shared.b16 {%0,%1,%2,%3}, [%4];"
                 : "=r"(r[0]), "=r"(r[1]), "=r"(r[2]), "=r"(r[3]) : "r"(addr));
}
__device__ __forceinline__ void mma16816(float* c, const uint32_t* a, const uint32_t* b) {
    asm volatile("mma.sync.aligned.m16n8k16.row.col.f32.bf16.bf16.f32 "
                 "{%0,%1,%2,%3}, {%4,%5,%6,%7}, {%8,%9}, {%0,%1,%2,%3};"
                 : "+f"(c[0]), "+f"(c[1]), "+f"(c[2]), "+f"(c[3])
                 : "r"(a[0]), "r"(a[1]), "r"(a[2]), "r"(a[3]), "r"(b[0]), "r"(b[1]));
}
// XOR swizzle for B tiles: rows of 64B (4x16B chunks) paired into 128B lines.
__device__ __forceinline__ uint32_t swz(int row, int c) {
    return ((row >> 1) << 7) + (((((row & 1) << 2) | c) ^ ((row >> 1) & 7)) << 4);
}
__device__ __forceinline__ float wred(float x) {
#pragma unroll
    for (int o = 16; o; o >>= 1) x += __shfl_xor_sync(0xFFFFFFFFu, x, o);
    return x;
}

// ---------------- merged prep: x transpose/split + W swizzle/split ----------------
__global__ __launch_bounds__(256) void prep_kernel(const float* __restrict__ x,
                                                   const float* __restrict__ W) {
    __shared__ float sT[32 * 65];
    const int tid = threadIdx.x;
    if (blockIdx.x < 4096) {
        const int n = blockIdx.x >> 6, h = blockIdx.x & 63;
#pragma unroll
        for (int k = 0; k < 8; ++k) {
            int idx = tid + k * 256;              // 2048 = 32 cin x 64 w
            int cin = idx >> 6, w = idx & 63;
            sT[cin * 65 + w] = x[((size_t)(n * 32 + cin)) * 4096 + h * 64 + w];
        }
        __syncthreads();
#pragma unroll
        for (int k = 0; k < 8; ++k) {
            int idx = tid + k * 256;
            int w = idx >> 5, cin = idx & 31;
            float v = sT[cin * 65 + w];
            __nv_bfloat16 hi = __float2bfloat16(v);
            float lo = v - __bfloat162float(hi);
            size_t o = ((size_t)blockIdx.x * 64 + w) * 32 + cin;
            g_xh[o] = hi;
            g_xl[o] = __float2bfloat16(lo);
        }
    } else {
        const int s = blockIdx.x - 4096;          // shift 0..24
        for (int e = tid; e < 16384; e += 256) {
            int prec = e >> 13, rem = e & 8191;
            int q = rem >> 3, i = rem & 7;        // 16B chunk q, element i
            int line = q >> 3, cf = q & 7;
            int t = cf ^ (line & 7);
            int row = line * 2 + (t >> 2);        // cout 0..255
            int c = t & 3;                        // cin chunk
            int cin = c * 8 + i;
            float v = W[row * 800 + cin * 25 + s];
            __nv_bfloat16 hi = __float2bfloat16(v);
            __nv_bfloat16 o = prec ? __float2bfloat16(v - __bfloat162float(hi)) : hi;
            g_wb[(s * 2 + prec) * 8192 + rem] = o;
        }
    }
}

// ---------------- conv: mma.sync bf16 implicit GEMM, 3-product hi/lo --------------
// R12 structure; ONLY change: product-major MMA order inside each nt group
// (same-accumulator reuse distance 2 -> 4; per-accumulator product order
// unchanged hh,lh,hl -> bit-identical result).
#define SA_BYTES 32640
#define SB_OFF   65280
#define SB_SLOT  16384
__global__ __launch_bounds__(256, 2) void conv_mma_kernel() {
    extern __shared__ char smem[];
    const uint32_t sb  = (uint32_t)__cvta_generic_to_shared(smem);
    const uint32_t sAh = sb, sAl = sb + SA_BYTES, sB = sb + SB_OFF;
    const int tid = threadIdx.x, wid = tid >> 5, lane = tid & 31;
    const int bx = blockIdx.x;
    const int nh = bx & 1;
    const int strip = bx >> 1;
    const int n = strip >> 5, h0 = (strip & 31) * 2;

    const __nv_bfloat16* xh = g_xh + (size_t)n * 4096 * 32;
    const __nv_bfloat16* xl = g_xl + (size_t)n * 4096 * 32;

    for (int i = tid; i < 1632; i += 256) {
        int cell = i >> 2, ch = i & 3;
        int r = cell / 68, c = cell - r * 68;
        int gh = h0 + r - 2, gw = c - 2;
        bool ok = ((unsigned)gh < 64u) && ((unsigned)gw < 64u);
        long eo = ok ? ((long)(gh * 64 + gw) * 32 + ch * 8) : 0;
        int sz = ok ? 16 : 0;
        uint32_t off = (uint32_t)(r * 68 + c) * 80 + ch * 16;
        cp16(sAh + off, xh + eo, sz);
        cp16(sAl + off, xl + eo, sz);
    }
    cp_commit();

    const char* wbase = (const char*)g_wb + nh * 8192;
    auto loadB = [&](int s, int slot) {
        const char* ws = wbase + (size_t)s * 32768;
        uint32_t d = sB + slot * SB_SLOT;
#pragma unroll
        for (int j = 0; j < 2; ++j) {
            uint32_t off = (uint32_t)(tid + j * 256) * 16;
            cp16(d + off,        ws + off,         16);
            cp16(d + 8192 + off, ws + 16384 + off, 16);
        }
    };
    loadB(0, 0); cp_commit();
    loadB(1, 1); cp_commit();

    const int mrow0 = (wid >> 1) * 32;
    const int ncol0 = (wid & 1) * 64;
    const int arow_off = (lane & 7) + ((lane >> 3) & 1) * 8;
    const int ac_off   = lane >> 4;
    const int brow_off = (lane & 7) + ((lane >> 4) << 3);
    const int bc_off   = (lane >> 3) & 1;

    int LA[2];
#pragma unroll
    for (int mt = 0; mt < 2; ++mt) {
        int m = mrow0 + mt * 16 + arow_off;
        LA[mt] = (m >> 6) * 68 + (m & 63);
    }

    float cacc[2][8][4];
#pragma unroll
    for (int a = 0; a < 2; ++a)
#pragma unroll
        for (int b = 0; b < 8; ++b)
#pragma unroll
            for (int d = 0; d < 4; ++d) cacc[a][b][d] = 0.0f;

#pragma unroll 1
    for (int s = 0; s < 25; ++s) {
        const int slot = s % 3;
        if (s < 24) cp_wait<1>(); else cp_wait<0>();
        __syncthreads();
        if (s + 2 < 25) { loadB(s + 2, (s + 2) % 3); cp_commit(); }

        const int ky = s / 5, kx = s - 5 * ky;
        const int soff = ky * 68 + kx;
        uint32_t arow[2];
#pragma unroll
        for (int mt = 0; mt < 2; ++mt) arow[mt] = (uint32_t)(LA[mt] + soff) * 80;

        uint32_t ah[2][2][4], al[2][2][4];
#pragma unroll
        for (int ks = 0; ks < 2; ++ks) {
            const uint32_t achunk = (uint32_t)(ks * 2 + ac_off) * 16;
#pragma unroll
            for (int mt = 0; mt < 2; ++mt) {
                ldsm4(ah[ks][mt], sAh + arow[mt] + achunk);
                ldsm4(al[ks][mt], sAl + arow[mt] + achunk);
            }
        }

        const uint32_t bbase = sB + slot * SB_SLOT;
#pragma unroll
        for (int ks = 0; ks < 2; ++ks) {
            const int cB = ks * 2 + bc_off;
#pragma unroll
            for (int nt = 0; nt < 4; ++nt) {
                uint32_t o = swz(ncol0 + nt * 16 + brow_off, cB);
                uint32_t bh[4], bl[4];
                ldsm4(bh, bbase + o);
                ldsm4(bl, bbase + 8192 + o);
                // product-major order: same-accumulator distance = 4 issue slots.
                // Per-accumulator sequence stays hh, lh, hl (bit-identical).
#pragma unroll
                for (int mt = 0; mt < 2; ++mt) {           // hh
                    mma16816(cacc[mt][2 * nt],     ah[ks][mt], bh);
                    mma16816(cacc[mt][2 * nt + 1], ah[ks][mt], bh + 2);
                }
#pragma unroll
                for (int mt = 0; mt < 2; ++mt) {           // lh
                    mma16816(cacc[mt][2 * nt],     al[ks][mt], bh);
                    mma16816(cacc[mt][2 * nt + 1], al[ks][mt], bh + 2);
                }
#pragma unroll
                for (int mt = 0; mt < 2; ++mt) {           // hl
                    mma16816(cacc[mt][2 * nt],     ah[ks][mt], bl);
                    mma16816(cacc[mt][2 * nt + 1], ah[ks][mt], bl + 2);
                }
            }
        }
    }

    const int g = lane >> 2, cc = (lane & 3) * 2;
#pragma unroll
    for (int mt = 0; mt < 2; ++mt) {
#pragma unroll
        for (int half = 0; half < 2; ++half) {
            int m = mrow0 + mt * 16 + g + half * 8;
            int pix = (h0 + (m >> 6)) * 64 + (m & 63);
            float* vp = g_votes + ((size_t)n * 4096 + pix) * 256 + nh * 128 + ncol0 + cc;
#pragma unroll
            for (int n8 = 0; n8 < 8; ++n8) {
                float2 v = make_float2(cacc[mt][n8][half * 2], cacc[mt][n8][half * 2 + 1]);
                *(float2*)(vp + n8 * 8) = v;
            }
        }
    }
}

// ---------------- routing v3 (R13, measured best): warp-pair per pixel ----------
__global__ __launch_bounds__(256, 3) void routing_kernel(const float* __restrict__ bias,
                                                         float* __restrict__ out) {
    extern __shared__ float rsm[];          // sv 8192 | ex 256 | sact 1024 floats
    float* sv   = rsm;
    float* ex   = rsm + 8192;
    float* sact = rsm + 8448;
    const uint32_t svb = (uint32_t)__cvta_generic_to_shared(rsm);

    const int tid = threadIdx.x, warp = tid >> 5, lane = tid & 31;
    const int pairid = warp >> 1, nh = warp & 1;       // nh: which nc-half
    const int b = blockIdx.x >> 10, h = (blockIdx.x >> 4) & 63, wq = blockIdx.x & 15;
    const int pixbase = h * 64 + wq * 4;
    const int pix = pixbase + pairid;

    // warp-local cp.async: 8 ic x 128 couts (this warp's nc-half) = 4KB/warp
#pragma unroll
    for (int ic = 0; ic < 8; ++ic) {
        const float* src = g_votes + ((size_t)(b * 8 + ic) * 4096 + pix) * 256
                         + nh * 128 + lane * 4;
        cp16(svb + (uint32_t)(warp * 4096 + ic * 512 + lane * 16), src, 16);
    }
    cp_commit();

    float bv[4];
#pragma unroll
    for (int ncl = 0; ncl < 4; ++ncl) bv[ncl] = bias[(nh * 4 + ncl) * 32 + lane];

    cp_wait<0>();
    __syncwarp();

    float v[8][4];
    const float* svp = sv + warp * 1024;
#pragma unroll
    for (int ic = 0; ic < 8; ++ic)
#pragma unroll
        for (int ncl = 0; ncl < 4; ++ncl)
            v[ic][ncl] = svp[ic * 128 + ncl * 32 + lane];

    const int my_ic = lane & 7;
    float lg[4];
#pragma unroll
    for (int ncl = 0; ncl < 4; ++ncl) lg[ncl] = 0.0f;
    float lgo[4];
#pragma unroll
    for (int ncl = 0; ncl < 4; ++ncl) lgo[ncl] = 0.0f;

    float a[4];
#pragma unroll 1
    for (int it = 0; it < 3; ++it) {
        float p[4];
#pragma unroll
        for (int ncl = 0; ncl < 4; ++ncl) p[ncl] = bv[ncl];

        if (it == 0) {                       // softmax of zeros = 0.125 exactly
#pragma unroll
            for (int ic = 0; ic < 8; ++ic)
#pragma unroll
                for (int ncl = 0; ncl < 4; ++ncl)
                    p[ncl] += 0.125f * v[ic][ncl];
        } else {
            float mx = lg[0];
#pragma unroll
            for (int ncl = 1; ncl < 4; ++ncl) mx = fmaxf(mx, lg[ncl]);
#pragma unroll
            for (int ncl = 0; ncl < 4; ++ncl) mx = fmaxf(mx, lgo[ncl]);
            float ssum = 0.0f;
            float r[4];
#pragma unroll
            for (int ncl = 0; ncl < 4; ++ncl) { r[ncl] = __expf(lg[ncl] - mx); ssum += r[ncl]; }
#pragma unroll
            for (int ncl = 0; ncl < 4; ++ncl) ssum += __expf(lgo[ncl] - mx);
            float inv = 1.0f / ssum;
#pragma unroll
            for (int ncl = 0; ncl < 4; ++ncl) r[ncl] *= inv;
#pragma unroll
            for (int ic = 0; ic < 8; ++ic)
#pragma unroll
                for (int ncl = 0; ncl < 4; ++ncl)
                    p[ncl] += __shfl_sync(0xFFFFFFFFu, r[ncl], ic) * v[ic][ncl];
        }
#pragma unroll
        for (int ncl = 0; ncl < 4; ++ncl) {
            float s2 = wred(p[ncl] * p[ncl]);
            a[ncl] = p[ncl] * (sqrtf(s2) / (1.0f + s2));
        }

        if (it < 2) {
            float z[16];
#pragma unroll
            for (int j = 0; j < 16; ++j) {
                int ncl = j & 3, icl = j >> 2;
                float pA = v[icl][ncl]     * a[ncl];
                float pB = v[icl + 4][ncl] * a[ncl];
                float send = (lane & 16) ? pA : pB;
                float recv = __shfl_xor_sync(0xFFFFFFFFu, send, 16);
                z[j] = ((lane & 16) ? pB : pA) + recv;
            }
#pragma unroll
            for (int o = 8; o; o >>= 1) {
#pragma unroll
                for (int j = 0; j < o; ++j) {
                    float send = (lane & o) ? z[j] : z[j + o];
                    float recv = __shfl_xor_sync(0xFFFFFFFFu, send, o);
                    z[j] = ((lane & o) ? z[j + o] : z[j]) + recv;
                }
            }
#pragma unroll
            for (int ncl = 0; ncl < 4; ++ncl)
                lg[ncl] += __shfl_sync(0xFFFFFFFFu, z[0], my_ic * 4 + ncl);

            if (lane < 8) {
#pragma unroll
                for (int ncl = 0; ncl < 4; ++ncl)
                    ex[pairid * 64 + lane * 8 + nh * 4 + ncl] = lg[ncl];
            }
            asm volatile("bar.sync %0, 64;" :: "r"(pairid + 1) : "memory");
#pragma unroll
            for (int ncl = 0; ncl < 4; ++ncl)
                lgo[ncl] = ex[pairid * 64 + my_ic * 8 + (1 - nh) * 4 + ncl];
        }
    }
#pragma unroll
    for (int ncl = 0; ncl < 4; ++ncl)
        sact[pairid * 256 + (nh * 4 + ncl) * 32 + lane] = a[ncl];
    __syncthreads();

    float4 o4 = make_float4(sact[0 * 256 + tid], sact[1 * 256 + tid],
                            sact[2 * 256 + tid], sact[3 * 256 + tid]);
    *(float4*)(out + ((size_t)b * 256 + tid) * 4096 + pixbase) = o4;
}

// ---------------------------------------------------------------------------
extern "C" void kernel_launch(void* const* d_in, const int* in_sizes, int n_in,
                              void* d_out, int out_size)
{
    const float* x    = (const float*)d_in[0];  // [8,8,32,64,64]
    const float* Wt   = (const float*)d_in[1];  // [256,32,5,5]
    const float* bias = (const float*)d_in[2];  // [1,1,8,32]
    float* out = (float*)d_out;                 // [8,8,32,64,64]

    const int conv_smem = 2 * SA_BYTES + 3 * SB_SLOT;        // 114432
    const int rout_smem = (8192 + 256 + 1024) * (int)sizeof(float);  // 37888
    cudaFuncSetAttribute(conv_mma_kernel,
                         cudaFuncAttributeMaxDynamicSharedMemorySize, conv_smem);
    cudaFuncSetAttribute(routing_kernel,
                         cudaFuncAttributeMaxDynamicSharedMemorySize, rout_smem);

    prep_kernel<<<4096 + 25, 256>>>(x, Wt);
    conv_mma_kernel<<<4096, 256, conv_smem>>>();
    routing_kernel<<<8 * 64 * 16, 256, rout_smem>>>(bias, out);
}

// round 17
// speedup vs baseline: 1.0513x; 1.0010x over previous
#include <cuda_runtime.h>
#include <cuda_bf16.h>
#include <stdint.h>
#include <math.h>

// ---------------- scratch ----------------
__device__ __align__(16) float         g_votes[(size_t)64 * 4096 * 256]; // [n][pix][cout]
__device__ __align__(16) __nv_bfloat16 g_xh[(size_t)64 * 4096 * 32];     // [n][h][w][cin] hi
__device__ __align__(16) __nv_bfloat16 g_xl[(size_t)64 * 4096 * 32];     // lo
__device__ __align__(16) __nv_bfloat16 g_wb[25 * 2 * 8192];              // [s][prec][swizzled 256x32]

// ---------------- helpers ----------------
__device__ __forceinline__ void cp16(uint32_t dst, const void* src, int sz) {
    asm volatile("cp.async.cg.shared.global [%0], [%1], 16, %2;"
                 :: "r"(dst), "l"(src), "r"(sz));
}
__device__ __forceinline__ void cp_commit() { asm volatile("cp.async.commit_group;" ::: "memory"); }
template <int N> __device__ __forceinline__ void cp_wait() {
    asm volatile("cp.async.wait_group %0;" :: "n"(N) : "memory");
}
__device__ __forceinline__ void ldsm4(uint32_t* r, uint32_t addr) {
    asm volatile("ldmatrix.sync.aligned.m8n8.x4.shared.b16 {%0,%1,%2,%3}, [%4];"
                 : "=r"(r[0]), "=r"(r[1]), "=r"(r[2]), "=r"(r[3]) : "r"(addr));
}
__device__ __forceinline__ void mma16816(float* c, const uint32_t* a, const uint32_t* b) {
    asm volatile("mma.sync.aligned.m16n8k16.row.col.f32.bf16.bf16.f32 "
                 "{%0,%1,%2,%3}, {%4,%5,%6,%7}, {%8,%9}, {%0,%1,%2,%3};"
                 : "+f"(c[0]), "+f"(c[1]), "+f"(c[2]), "+f"(c[3])
                 : "r"(a[0]), "r"(a[1]), "r"(a[2]), "r"(a[3]), "r"(b[0]), "r"(b[1]));
}
// XOR swizzle for B tiles: rows of 64B (4x16B chunks) paired into 128B lines.
__device__ __forceinline__ uint32_t swz(int row, int c) {
    return ((row >> 1) << 7) + (((((row & 1) << 2) | c) ^ ((row >> 1) & 7)) << 4);
}
__device__ __forceinline__ float wred(float x) {
#pragma unroll
    for (int o = 16; o; o >>= 1) x += __shfl_xor_sync(0xFFFFFFFFu, x, o);
    return x;
}

// ---------------- merged prep: x transpose/split + W swizzle/split ----------------
// Vectorized: float2 loads, bf16x2 stores (prep is issue-bound, not BW-bound).
__global__ __launch_bounds__(256) void prep_kernel(const float* __restrict__ x,
                                                   const float* __restrict__ W) {
    __shared__ float sT[32 * 65];
    const int tid = threadIdx.x;
    if (blockIdx.x < 4096) {
        const int n = blockIdx.x >> 6, h = blockIdx.x & 63;
#pragma unroll
        for (int k = 0; k < 4; ++k) {
            int idx = tid + k * 256;              // 1024 = 32 cin x 32 w-pairs
            int cin = idx >> 5, wp = idx & 31;
            float2 v2 = *(const float2*)(x + ((size_t)(n * 32 + cin)) * 4096
                                           + h * 64 + wp * 2);
            sT[cin * 65 + wp * 2]     = v2.x;
            sT[cin * 65 + wp * 2 + 1] = v2.y;
        }
        __syncthreads();
#pragma unroll
        for (int k = 0; k < 4; ++k) {
            int idx = tid + k * 256;              // 1024 = 64 w x 16 cin-pairs
            int w = idx >> 4, cp = idx & 15;
            int cin0 = cp * 2;
            float v0 = sT[cin0 * 65 + w];
            float v1 = sT[(cin0 + 1) * 65 + w];
            __nv_bfloat16 h0 = __float2bfloat16(v0);
            __nv_bfloat16 h1 = __float2bfloat16(v1);
            __nv_bfloat162 hi2; hi2.x = h0; hi2.y = h1;
            __nv_bfloat162 lo2;
            lo2.x = __float2bfloat16(v0 - __bfloat162float(h0));
            lo2.y = __float2bfloat16(v1 - __bfloat162float(h1));
            size_t o2 = ((size_t)blockIdx.x * 64 + w) * 16 + cp;
            ((__nv_bfloat162*)g_xh)[o2] = hi2;
            ((__nv_bfloat162*)g_xl)[o2] = lo2;
        }
    } else {
        const int s = blockIdx.x - 4096;          // shift 0..24
        for (int e = tid; e < 16384; e += 256) {
            int prec = e >> 13, rem = e & 8191;
            int q = rem >> 3, i = rem & 7;        // 16B chunk q, element i
            int line = q >> 3, cf = q & 7;
            int t = cf ^ (line & 7);
            int row = line * 2 + (t >> 2);        // cout 0..255
            int c = t & 3;                        // cin chunk
            int cin = c * 8 + i;
            float v = W[row * 800 + cin * 25 + s];
            __nv_bfloat16 hi = __float2bfloat16(v);
            __nv_bfloat16 o = prec ? __float2bfloat16(v - __bfloat162float(hi)) : hi;
            g_wb[(s * 2 + prec) * 8192 + rem] = o;
        }
    }
}

// ---------------- conv: mma.sync bf16 implicit GEMM, 3-product hi/lo --------------
// R16 structure (measured best); epilogue stores votes with __stcs (streaming).
#define SA_BYTES 32640
#define SB_OFF   65280
#define SB_SLOT  16384
__global__ __launch_bounds__(256, 2) void conv_mma_kernel() {
    extern __shared__ char smem[];
    const uint32_t sb  = (uint32_t)__cvta_generic_to_shared(smem);
    const uint32_t sAh = sb, sAl = sb + SA_BYTES, sB = sb + SB_OFF;
    const int tid = threadIdx.x, wid = tid >> 5, lane = tid & 31;
    const int bx = blockIdx.x;
    const int nh = bx & 1;
    const int strip = bx >> 1;
    const int n = strip >> 5, h0 = (strip & 31) * 2;

    const __nv_bfloat16* xh = g_xh + (size_t)n * 4096 * 32;
    const __nv_bfloat16* xl = g_xl + (size_t)n * 4096 * 32;

    for (int i = tid; i < 1632; i += 256) {
        int cell = i >> 2, ch = i & 3;
        int r = cell / 68, c = cell - r * 68;
        int gh = h0 + r - 2, gw = c - 2;
        bool ok = ((unsigned)gh < 64u) && ((unsigned)gw < 64u);
        long eo = ok ? ((long)(gh * 64 + gw) * 32 + ch * 8) : 0;
        int sz = ok ? 16 : 0;
        uint32_t off = (uint32_t)(r * 68 + c) * 80 + ch * 16;
        cp16(sAh + off, xh + eo, sz);
        cp16(sAl + off, xl + eo, sz);
    }
    cp_commit();

    const char* wbase = (const char*)g_wb + nh * 8192;
    auto loadB = [&](int s, int slot) {
        const char* ws = wbase + (size_t)s * 32768;
        uint32_t d = sB + slot * SB_SLOT;
#pragma unroll
        for (int j = 0; j < 2; ++j) {
            uint32_t off = (uint32_t)(tid + j * 256) * 16;
            cp16(d + off,        ws + off,         16);
            cp16(d + 8192 + off, ws + 16384 + off, 16);
        }
    };
    loadB(0, 0); cp_commit();
    loadB(1, 1); cp_commit();

    const int mrow0 = (wid >> 1) * 32;
    const int ncol0 = (wid & 1) * 64;
    const int arow_off = (lane & 7) + ((lane >> 3) & 1) * 8;
    const int ac_off   = lane >> 4;
    const int brow_off = (lane & 7) + ((lane >> 4) << 3);
    const int bc_off   = (lane >> 3) & 1;

    int LA[2];
#pragma unroll
    for (int mt = 0; mt < 2; ++mt) {
        int m = mrow0 + mt * 16 + arow_off;
        LA[mt] = (m >> 6) * 68 + (m & 63);
    }

    float cacc[2][8][4];
#pragma unroll
    for (int a = 0; a < 2; ++a)
#pragma unroll
        for (int b = 0; b < 8; ++b)
#pragma unroll
            for (int d = 0; d < 4; ++d) cacc[a][b][d] = 0.0f;

#pragma unroll 1
    for (int s = 0; s < 25; ++s) {
        const int slot = s % 3;
        if (s < 24) cp_wait<1>(); else cp_wait<0>();
        __syncthreads();
        if (s + 2 < 25) { loadB(s + 2, (s + 2) % 3); cp_commit(); }

        const int ky = s / 5, kx = s - 5 * ky;
        const int soff = ky * 68 + kx;
        uint32_t arow[2];
#pragma unroll
        for (int mt = 0; mt < 2; ++mt) arow[mt] = (uint32_t)(LA[mt] + soff) * 80;

        uint32_t ah[2][2][4], al[2][2][4];
#pragma unroll
        for (int ks = 0; ks < 2; ++ks) {
            const uint32_t achunk = (uint32_t)(ks * 2 + ac_off) * 16;
#pragma unroll
            for (int mt = 0; mt < 2; ++mt) {
                ldsm4(ah[ks][mt], sAh + arow[mt] + achunk);
                ldsm4(al[ks][mt], sAl + arow[mt] + achunk);
            }
        }

        const uint32_t bbase = sB + slot * SB_SLOT;
#pragma unroll
        for (int ks = 0; ks < 2; ++ks) {
            const int cB = ks * 2 + bc_off;
#pragma unroll
            for (int nt = 0; nt < 4; ++nt) {
                uint32_t o = swz(ncol0 + nt * 16 + brow_off, cB);
                uint32_t bh[4], bl[4];
                ldsm4(bh, bbase + o);
                ldsm4(bl, bbase + 8192 + o);
#pragma unroll
                for (int mt = 0; mt < 2; ++mt) {           // hh
                    mma16816(cacc[mt][2 * nt],     ah[ks][mt], bh);
                    mma16816(cacc[mt][2 * nt + 1], ah[ks][mt], bh + 2);
                }
#pragma unroll
                for (int mt = 0; mt < 2; ++mt) {           // lh
                    mma16816(cacc[mt][2 * nt],     al[ks][mt], bh);
                    mma16816(cacc[mt][2 * nt + 1], al[ks][mt], bh + 2);
                }
#pragma unroll
                for (int mt = 0; mt < 2; ++mt) {           // hl
                    mma16816(cacc[mt][2 * nt],     ah[ks][mt], bl);
                    mma16816(cacc[mt][2 * nt + 1], ah[ks][mt], bl + 2);
                }
            }
        }
    }

    const int g = lane >> 2, cc = (lane & 3) * 2;
#pragma unroll
    for (int mt = 0; mt < 2; ++mt) {
#pragma unroll
        for (int half = 0; half < 2; ++half) {
            int m = mrow0 + mt * 16 + g + half * 8;
            int pix = (h0 + (m >> 6)) * 64 + (m & 63);
            float* vp = g_votes + ((size_t)n * 4096 + pix) * 256 + nh * 128 + ncol0 + cc;
#pragma unroll
            for (int n8 = 0; n8 < 8; ++n8) {
                float2 v = make_float2(cacc[mt][n8][half * 2], cacc[mt][n8][half * 2 + 1]);
                __stcs(reinterpret_cast<float2*>(vp + n8 * 8), v);
            }
        }
    }
}

// ---------------- routing v3 (R13, measured best): warp-pair per pixel ----------
__global__ __launch_bounds__(256, 3) void routing_kernel(const float* __restrict__ bias,
                                                         float* __restrict__ out) {
    extern __shared__ float rsm[];          // sv 8192 | ex 256 | sact 1024 floats
    float* sv   = rsm;
    float* ex   = rsm + 8192;
    float* sact = rsm + 8448;
    const uint32_t svb = (uint32_t)__cvta_generic_to_shared(rsm);

    const int tid = threadIdx.x, warp = tid >> 5, lane = tid & 31;
    const int pairid = warp >> 1, nh = warp & 1;       // nh: which nc-half
    const int b = blockIdx.x >> 10, h = (blockIdx.x >> 4) & 63, wq = blockIdx.x & 15;
    const int pixbase = h * 64 + wq * 4;
    const int pix = pixbase + pairid;

    // warp-local cp.async: 8 ic x 128 couts (this warp's nc-half) = 4KB/warp
#pragma unroll
    for (int ic = 0; ic < 8; ++ic) {
        const float* src = g_votes + ((size_t)(b * 8 + ic) * 4096 + pix) * 256
                         + nh * 128 + lane * 4;
        cp16(svb + (uint32_t)(warp * 4096 + ic * 512 + lane * 16), src, 16);
    }
    cp_commit();

    float bv[4];
#pragma unroll
    for (int ncl = 0; ncl < 4; ++ncl) bv[ncl] = bias[(nh * 4 + ncl) * 32 + lane];

    cp_wait<0>();
    __syncwarp();

    float v[8][4];
    const float* svp = sv + warp * 1024;
#pragma unroll
    for (int ic = 0; ic < 8; ++ic)
#pragma unroll
        for (int ncl = 0; ncl < 4; ++ncl)
            v[ic][ncl] = svp[ic * 128 + ncl * 32 + lane];

    const int my_ic = lane & 7;
    float lg[4];
#pragma unroll
    for (int ncl = 0; ncl < 4; ++ncl) lg[ncl] = 0.0f;
    float lgo[4];
#pragma unroll
    for (int ncl = 0; ncl < 4; ++ncl) lgo[ncl] = 0.0f;

    float a[4];
#pragma unroll 1
    for (int it = 0; it < 3; ++it) {
        float p[4];
#pragma unroll
        for (int ncl = 0; ncl < 4; ++ncl) p[ncl] = bv[ncl];

        if (it == 0) {                       // softmax of zeros = 0.125 exactly
#pragma unroll
            for (int ic = 0; ic < 8; ++ic)
#pragma unroll
                for (int ncl = 0; ncl < 4; ++ncl)
                    p[ncl] += 0.125f * v[ic][ncl];
        } else {
            float mx = lg[0];
#pragma unroll
            for (int ncl = 1; ncl < 4; ++ncl) mx = fmaxf(mx, lg[ncl]);
#pragma unroll
            for (int ncl = 0; ncl < 4; ++ncl) mx = fmaxf(mx, lgo[ncl]);
            float ssum = 0.0f;
            float r[4];
#pragma unroll
            for (int ncl = 0; ncl < 4; ++ncl) { r[ncl] = __expf(lg[ncl] - mx); ssum += r[ncl]; }
#pragma unroll
            for (int ncl = 0; ncl < 4; ++ncl) ssum += __expf(lgo[ncl] - mx);
            float inv = 1.0f / ssum;
#pragma unroll
            for (int ncl = 0; ncl < 4; ++ncl) r[ncl] *= inv;
#pragma unroll
            for (int ic = 0; ic < 8; ++ic)
#pragma unroll
                for (int ncl = 0; ncl < 4; ++ncl)
                    p[ncl] += __shfl_sync(0xFFFFFFFFu, r[ncl], ic) * v[ic][ncl];
        }
#pragma unroll
        for (int ncl = 0; ncl < 4; ++ncl) {
            float s2 = wred(p[ncl] * p[ncl]);
            a[ncl] = p[ncl] * (sqrtf(s2) / (1.0f + s2));
        }

        if (it < 2) {
            float z[16];
#pragma unroll
            for (int j = 0; j < 16; ++j) {
                int ncl = j & 3, icl = j >> 2;
                float pA = v[icl][ncl]     * a[ncl];
                float pB = v[icl + 4][ncl] * a[ncl];
                float send = (lane & 16) ? pA : pB;
                float recv = __shfl_xor_sync(0xFFFFFFFFu, send, 16);
                z[j] = ((lane & 16) ? pB : pA) + recv;
            }
#pragma unroll
            for (int o = 8; o; o >>= 1) {
#pragma unroll
                for (int j = 0; j < o; ++j) {
                    float send = (lane & o) ? z[j] : z[j + o];
                    float recv = __shfl_xor_sync(0xFFFFFFFFu, send, o);
                    z[j] = ((lane & o) ? z[j + o] : z[j]) + recv;
                }
            }
#pragma unroll
            for (int ncl = 0; ncl < 4; ++ncl)
                lg[ncl] += __shfl_sync(0xFFFFFFFFu, z[0], my_ic * 4 + ncl);

            if (lane < 8) {
#pragma unroll
                for (int ncl = 0; ncl < 4; ++ncl)
                    ex[pairid * 64 + lane * 8 + nh * 4 + ncl] = lg[ncl];
            }
            asm volatile("bar.sync %0, 64;" :: "r"(pairid + 1) : "memory");
#pragma unroll
            for (int ncl = 0; ncl < 4; ++ncl)
                lgo[ncl] = ex[pairid * 64 + my_ic * 8 + (1 - nh) * 4 + ncl];
        }
    }
#pragma unroll
    for (int ncl = 0; ncl < 4; ++ncl)
        sact[pairid * 256 + (nh * 4 + ncl) * 32 + lane] = a[ncl];
    __syncthreads();

    float4 o4 = make_float4(sact[0 * 256 + tid], sact[1 * 256 + tid],
                            sact[2 * 256 + tid], sact[3 * 256 + tid]);
    *(float4*)(out + ((size_t)b * 256 + tid) * 4096 + pixbase) = o4;
}

// ---------------------------------------------------------------------------
extern "C" void kernel_launch(void* const* d_in, const int* in_sizes, int n_in,
                              void* d_out, int out_size)
{
    const float* x    = (const float*)d_in[0];  // [8,8,32,64,64]
    const float* Wt   = (const float*)d_in[1];  // [256,32,5,5]
    const float* bias = (const float*)d_in[2];  // [1,1,8,32]
    float* out = (float*)d_out;                 // [8,8,32,64,64]

    const int conv_smem = 2 * SA_BYTES + 3 * SB_SLOT;        // 114432
    const int rout_smem = (8192 + 256 + 1024) * (int)sizeof(float);  // 37888
    cudaFuncSetAttribute(conv_mma_kernel,
                         cudaFuncAttributeMaxDynamicSharedMemorySize, conv_smem);
    cudaFuncSetAttribute(routing_kernel,
                         cudaFuncAttributeMaxDynamicSharedMemorySize, rout_smem);

    prep_kernel<<<4096 + 25, 256>>>(x, Wt);
    conv_mma_kernel<<<4096, 256, conv_smem>>>();
    routing_kernel<<<8 * 64 * 16, 256, rout_smem>>>(bias, out);
}